// round 1
// baseline (speedup 1.0000x reference)
#include <cuda_runtime.h>
#include <math.h>

#define NN   50000
#define NE   800000
#define DIM  128
#define HID  128
#define ODIM 64
#define NL   3
#define NPB  8   // nodes per block in dense kernels

// Scratch (no allocation allowed)
__device__ float g_h[(size_t)NN * HID];
__device__ float g_agg[(size_t)NN * HID];
__device__ float g_cnt[NN];

__device__ __forceinline__ float gelu_f(float x) {
    return 0.5f * x * (1.0f + erff(x * 0.70710678118654752440f));
}

// ---------------------------------------------------------------------------
// In-degree count: one thread per edge
// ---------------------------------------------------------------------------
__global__ __launch_bounds__(256) void count_kernel(const int* __restrict__ dst) {
    int e = blockIdx.x * blockDim.x + threadIdx.x;
    if (e < NE) atomicAdd(&g_cnt[dst[e]], 1.0f);
}

// ---------------------------------------------------------------------------
// Fused: layernorm(x) -> @ in_proj + b -> gelu -> g_h
// 8 nodes / block of 128 threads. Warp w handles LN for rows w and w+4.
// ---------------------------------------------------------------------------
__global__ __launch_bounds__(128) void input_kernel(
    const float* __restrict__ x,
    const float* __restrict__ lng, const float* __restrict__ lnb,
    const float* __restrict__ W,   const float* __restrict__ pb)
{
    __shared__ __align__(16) float sm[NPB][DIM];
    int nb = blockIdx.x * NPB;
    int tid = threadIdx.x, w = tid >> 5, lane = tid & 31;

#pragma unroll
    for (int rr = 0; rr < 2; rr++) {
        int r = w + rr * 4;
        int node = nb + r;
        int c = lane * 4;
        float4 v = make_float4(0.f, 0.f, 0.f, 0.f);
        if (node < NN) v = *(const float4*)(x + (size_t)node * DIM + c);
        float s  = v.x + v.y + v.z + v.w;
        float sq = v.x*v.x + v.y*v.y + v.z*v.z + v.w*v.w;
#pragma unroll
        for (int o = 16; o > 0; o >>= 1) {
            s  += __shfl_xor_sync(0xffffffffu, s,  o);
            sq += __shfl_xor_sync(0xffffffffu, sq, o);
        }
        float m    = s * (1.0f / DIM);
        float rstd = rsqrtf(sq * (1.0f / DIM) - m * m + 1e-5f);
        float4 o4;
        o4.x = (v.x - m) * rstd * lng[c + 0] + lnb[c + 0];
        o4.y = (v.y - m) * rstd * lng[c + 1] + lnb[c + 1];
        o4.z = (v.z - m) * rstd * lng[c + 2] + lnb[c + 2];
        o4.w = (v.w - m) * rstd * lng[c + 3] + lnb[c + 3];
        *(float4*)&sm[r][c] = o4;
    }
    __syncthreads();

    int j = tid;
    float bias = pb[j];
    float acc[NPB];
#pragma unroll
    for (int r = 0; r < NPB; r++) acc[r] = bias;

#pragma unroll 4
    for (int k = 0; k < DIM; k += 4) {
        float w0 = W[(k + 0) * HID + j];
        float w1 = W[(k + 1) * HID + j];
        float w2 = W[(k + 2) * HID + j];
        float w3 = W[(k + 3) * HID + j];
#pragma unroll
        for (int r = 0; r < NPB; r++) {
            float4 hv = *(const float4*)&sm[r][k];
            acc[r] += hv.x * w0 + hv.y * w1 + hv.z * w2 + hv.w * w3;
        }
    }
#pragma unroll
    for (int r = 0; r < NPB; r++) {
        int node = nb + r;
        if (node < NN) g_h[(size_t)node * HID + j] = gelu_f(acc[r]);
    }
}

// ---------------------------------------------------------------------------
// Scatter-add: warp per edge. Coalesced 512B gather of h[src], vector
// red.global.add.v4.f32 into agg[dst].
// ---------------------------------------------------------------------------
__global__ __launch_bounds__(256) void scatter_kernel(
    const int* __restrict__ src, const int* __restrict__ dst)
{
    int idx = blockIdx.x * blockDim.x + threadIdx.x;
    int e = idx >> 5;
    if (e >= NE) return;
    int c = (idx & 31) * 4;
    int s = __ldg(src + e);
    int d = __ldg(dst + e);
    float4 v = *(const float4*)(g_h + (size_t)s * HID + c);
    float* p = g_agg + (size_t)d * HID + c;
    asm volatile("red.global.add.v4.f32 [%0], {%1, %2, %3, %4};"
                 :: "l"(p), "f"(v.x), "f"(v.y), "f"(v.z), "f"(v.w)
                 : "memory");
}

// ---------------------------------------------------------------------------
// Fused SAGE layer tail: mean = agg/max(cnt,1); t = mean@Wl + bl + h@Wr;
// h = gelu(layernorm(t)) + h.  8 nodes / block of 128 threads.
// ---------------------------------------------------------------------------
__global__ __launch_bounds__(128) void combine_kernel(
    const float* __restrict__ Wl, const float* __restrict__ bl,
    const float* __restrict__ Wr,
    const float* __restrict__ ng, const float* __restrict__ nbeta)
{
    __shared__ __align__(16) float sm_m[NPB][DIM];
    __shared__ __align__(16) float sm_r[NPB][DIM];
    int nb = blockIdx.x * NPB;
    int tid = threadIdx.x, w = tid >> 5, lane = tid & 31;

    // Phase 1: load mean (agg * 1/cnt) and root rows into smem
#pragma unroll
    for (int rr = 0; rr < 2; rr++) {
        int r = w + rr * 4;
        int node = nb + r;
        int c = lane * 4;
        float4 a = make_float4(0.f, 0.f, 0.f, 0.f);
        float4 h = make_float4(0.f, 0.f, 0.f, 0.f);
        float inv = 0.f;
        if (node < NN) {
            inv = 1.0f / fmaxf(g_cnt[node], 1.0f);
            a = *(const float4*)(g_agg + (size_t)node * HID + c);
            h = *(const float4*)(g_h   + (size_t)node * HID + c);
        }
        a.x *= inv; a.y *= inv; a.z *= inv; a.w *= inv;
        *(float4*)&sm_m[r][c] = a;
        *(float4*)&sm_r[r][c] = h;
    }
    __syncthreads();

    // Phase 2: dual matvec, thread j = output column, 8 rows
    int j = tid;
    float bias = bl[j];
    float acc[NPB];
#pragma unroll
    for (int r = 0; r < NPB; r++) acc[r] = bias;

#pragma unroll 4
    for (int k = 0; k < DIM; k += 4) {
        float l0 = Wl[(k + 0) * HID + j];
        float l1 = Wl[(k + 1) * HID + j];
        float l2 = Wl[(k + 2) * HID + j];
        float l3 = Wl[(k + 3) * HID + j];
        float r0 = Wr[(k + 0) * HID + j];
        float r1 = Wr[(k + 1) * HID + j];
        float r2 = Wr[(k + 2) * HID + j];
        float r3 = Wr[(k + 3) * HID + j];
#pragma unroll
        for (int r = 0; r < NPB; r++) {
            float4 mv = *(const float4*)&sm_m[r][k];
            float4 hv = *(const float4*)&sm_r[r][k];
            acc[r] += mv.x * l0 + mv.y * l1 + mv.z * l2 + mv.w * l3
                    + hv.x * r0 + hv.y * r1 + hv.z * r2 + hv.w * r3;
        }
    }
    __syncthreads();
#pragma unroll
    for (int r = 0; r < NPB; r++) sm_m[r][j] = acc[r];
    __syncthreads();

    // Phase 3: per-row LN + gelu + residual, write back to g_h
#pragma unroll
    for (int rr = 0; rr < 2; rr++) {
        int r = w + rr * 4;
        int node = nb + r;
        int c = lane * 4;
        float4 v = *(const float4*)&sm_m[r][c];
        float s  = v.x + v.y + v.z + v.w;
        float sq = v.x*v.x + v.y*v.y + v.z*v.z + v.w*v.w;
#pragma unroll
        for (int o = 16; o > 0; o >>= 1) {
            s  += __shfl_xor_sync(0xffffffffu, s,  o);
            sq += __shfl_xor_sync(0xffffffffu, sq, o);
        }
        float m    = s * (1.0f / HID);
        float rstd = rsqrtf(sq * (1.0f / HID) - m * m + 1e-5f);
        float4 hres = *(const float4*)&sm_r[r][c];
        float4 o4;
        o4.x = gelu_f((v.x - m) * rstd * ng[c + 0] + nbeta[c + 0]) + hres.x;
        o4.y = gelu_f((v.y - m) * rstd * ng[c + 1] + nbeta[c + 1]) + hres.y;
        o4.z = gelu_f((v.z - m) * rstd * ng[c + 2] + nbeta[c + 2]) + hres.z;
        o4.w = gelu_f((v.w - m) * rstd * ng[c + 3] + nbeta[c + 3]) + hres.w;
        if (node < NN) *(float4*)(g_h + (size_t)node * HID + c) = o4;
    }
}

// ---------------------------------------------------------------------------
// Fused: layernorm(h) @ out_proj + b -> out.  8 nodes / block of 128 threads;
// 64 output cols, so threads split: half 0 -> rows 0..3, half 1 -> rows 4..7.
// ---------------------------------------------------------------------------
__global__ __launch_bounds__(128) void final_kernel(
    const float* __restrict__ lng, const float* __restrict__ lnb,
    const float* __restrict__ W,   const float* __restrict__ pb,
    float* __restrict__ out)
{
    __shared__ __align__(16) float sm[NPB][DIM];
    int nb = blockIdx.x * NPB;
    int tid = threadIdx.x, w = tid >> 5, lane = tid & 31;

#pragma unroll
    for (int rr = 0; rr < 2; rr++) {
        int r = w + rr * 4;
        int node = nb + r;
        int c = lane * 4;
        float4 v = make_float4(0.f, 0.f, 0.f, 0.f);
        if (node < NN) v = *(const float4*)(g_h + (size_t)node * HID + c);
        float s  = v.x + v.y + v.z + v.w;
        float sq = v.x*v.x + v.y*v.y + v.z*v.z + v.w*v.w;
#pragma unroll
        for (int o = 16; o > 0; o >>= 1) {
            s  += __shfl_xor_sync(0xffffffffu, s,  o);
            sq += __shfl_xor_sync(0xffffffffu, sq, o);
        }
        float m    = s * (1.0f / HID);
        float rstd = rsqrtf(sq * (1.0f / HID) - m * m + 1e-5f);
        float4 o4;
        o4.x = (v.x - m) * rstd * lng[c + 0] + lnb[c + 0];
        o4.y = (v.y - m) * rstd * lng[c + 1] + lnb[c + 1];
        o4.z = (v.z - m) * rstd * lng[c + 2] + lnb[c + 2];
        o4.w = (v.w - m) * rstd * lng[c + 3] + lnb[c + 3];
        *(float4*)&sm[r][c] = o4;
    }
    __syncthreads();

    int jj   = tid & 63;
    int half = tid >> 6;  // 0: rows 0-3, 1: rows 4-7
    float bias = pb[jj];
    float acc[4];
#pragma unroll
    for (int r = 0; r < 4; r++) acc[r] = bias;

#pragma unroll 4
    for (int k = 0; k < HID; k += 4) {
        float w0 = W[(k + 0) * ODIM + jj];
        float w1 = W[(k + 1) * ODIM + jj];
        float w2 = W[(k + 2) * ODIM + jj];
        float w3 = W[(k + 3) * ODIM + jj];
#pragma unroll
        for (int r = 0; r < 4; r++) {
            float4 hv = *(const float4*)&sm[half * 4 + r][k];
            acc[r] += hv.x * w0 + hv.y * w1 + hv.z * w2 + hv.w * w3;
        }
    }
#pragma unroll
    for (int r = 0; r < 4; r++) {
        int node = nb + half * 4 + r;
        if (node < NN) out[(size_t)node * ODIM + jj] = acc[r];
    }
}

// ---------------------------------------------------------------------------
extern "C" void kernel_launch(void* const* d_in, const int* in_sizes, int n_in,
                              void* d_out, int out_size)
{
    const float* x     = (const float*)d_in[0];
    const int*   ei    = (const int*)  d_in[1];
    const float* in_g  = (const float*)d_in[2];
    const float* in_b  = (const float*)d_in[3];
    const float* inW   = (const float*)d_in[4];
    const float* inPb  = (const float*)d_in[5];
    const float* Wl    = (const float*)d_in[6];
    const float* bl    = (const float*)d_in[7];
    const float* Wr    = (const float*)d_in[8];
    const float* ng    = (const float*)d_in[9];
    const float* nbta  = (const float*)d_in[10];
    const float* og    = (const float*)d_in[11];
    const float* ob    = (const float*)d_in[12];
    const float* oW    = (const float*)d_in[13];
    const float* oPb   = (const float*)d_in[14];
    float* out = (float*)d_out;

    const int* src = ei;
    const int* dst = ei + NE;

    void* cntp = nullptr;
    void* aggp = nullptr;
    cudaGetSymbolAddress(&cntp, g_cnt);
    cudaGetSymbolAddress(&aggp, g_agg);

    const int nblk = (NN + NPB - 1) / NPB;          // 6250
    const int sblk = (NE * 32 + 255) / 256;         // 100000

    cudaMemsetAsync(cntp, 0, NN * sizeof(float));
    count_kernel<<<(NE + 255) / 256, 256>>>(dst);
    input_kernel<<<nblk, 128>>>(x, in_g, in_b, inW, inPb);

    for (int l = 0; l < NL; l++) {
        cudaMemsetAsync(aggp, 0, (size_t)NN * HID * sizeof(float));
        scatter_kernel<<<sblk, 256>>>(src, dst);
        combine_kernel<<<nblk, 128>>>(Wl + (size_t)l * HID * HID,
                                      bl + l * HID,
                                      Wr + (size_t)l * HID * HID,
                                      ng + l * HID,
                                      nbta + l * HID);
    }

    final_kernel<<<nblk, 128>>>(og, ob, oW, oPb, out);
}